// round 8
// baseline (speedup 1.0000x reference)
#include <cuda_runtime.h>

// fired[b,s,r] = x[...,i] * x[...,5+j] * x[...,10+k],  r = i*25 + j*5 + k
// Exact zeros in x act as identity (reference: where(rpu==0,1,rpu)).
//
// R7: thread t = rule t (one decomposition per thread, ~10 ALU total).
// 128-thread CTAs, 16 positions each, grid=2048 = one full wave at occ 16.
// Inner body per position: 3 LDS [R+imm] + 2 FMUL + 1 STG [R+imm] — all
// position strides are compile-time immediates. Warp stores are 128B
// contiguous -> fully coalesced. ~3x fewer instructions than R3/R6.

static constexpr int F    = 15;           // membership functions per position
static constexpr int R    = 125;          // rules per position
static constexpr int G    = 16;           // positions per CTA
static constexpr int NLD4 = G * F / 4;    // 60 float4 input loads per CTA

__global__ void __launch_bounds__(128, 16)
rules_fire_v7(const float4* __restrict__ x4, float* __restrict__ out)
{
    __shared__ float sx[G * F];           // 240 floats (16 rows x 15)

    const int t   = threadIdx.x;
    const int grp = blockIdx.x;

    // Stage 16x15 inputs (threads 0..59), zero->1 fix at load.
    if (t < NLD4) {
        float4 v = x4[(size_t)grp * NLD4 + t];
        v.x = (v.x == 0.0f) ? 1.0f : v.x;
        v.y = (v.y == 0.0f) ? 1.0f : v.y;
        v.z = (v.z == 0.0f) ? 1.0f : v.z;
        v.w = (v.w == 0.0f) ? 1.0f : v.w;
        reinterpret_cast<float4*>(sx)[t] = v;
    }
    __syncthreads();

    if (t < R) {
        // One rule decomposition per thread — the only divisions in the kernel.
        const int q = t / 5;
        const int k = t - 5 * q;          // t % 5
        const int i = q / 5;
        const int j = q - 5 * i;          // (t/5) % 5
        const float* base = sx;           // row p lives at base + p*F (imm)

        // ab/c smem offsets, fixed per thread; p-stride folds into immediates.
        const int oa = i;
        const int ob = 5 + j;
        const int oc = 10 + k;

        float* o = out + (size_t)grp * G * R + t;   // + p*R via immediates

        #pragma unroll
        for (int p = 0; p < G; p++) {
            const int rb = p * F;
            o[p * R] = base[rb + oa] * base[rb + ob] * base[rb + oc];
        }
    }
}

// Scalar fallback for positions past the last full group (unused for B=16,S=2048).
__global__ void rules_fire_tail(const float* __restrict__ x, float* __restrict__ out,
                                int pos0, int npos)
{
    const int pos = pos0 + blockIdx.x;
    if (pos >= npos) return;
    __shared__ float sxt[F + 1];
    const int t = threadIdx.x;
    if (t < F) {
        float v = x[(size_t)pos * F + t];
        sxt[t] = (v == 0.0f) ? 1.0f : v;
    }
    __syncthreads();
    if (t < R) {
        const int i = t / 25, j = (t / 5) % 5, k = t % 5;
        out[(size_t)pos * R + t] = sxt[i] * sxt[5 + j] * sxt[10 + k];
    }
}

extern "C" void kernel_launch(void* const* d_in, const int* in_sizes, int n_in,
                              void* d_out, int out_size)
{
    const float* x = (const float*)d_in[0];   // (B, S, 15) float32
    float* out = (float*)d_out;               // (B, S, 125) float32

    const int npos    = in_sizes[0] / F;      // 32768
    const int ngroups = npos / G;             // 2048
    if (ngroups > 0)
        rules_fire_v7<<<ngroups, 128>>>((const float4*)x, out);

    const int tail = npos - ngroups * G;
    if (tail > 0)
        rules_fire_tail<<<tail, 128>>>(x, out, ngroups * G, npos);
}

// round 9
// speedup vs baseline: 1.0294x; 1.0294x over previous
#include <cuda_runtime.h>

// fired[b,s,r] = x[...,i] * x[...,5+j] * x[...,10+k],  r = i*25 + j*5 + k
// Exact zeros in x act as identity (reference: where(rpu==0,1,rpu)).
//
// R7 lesson: instruction count is NOT the limiter (issue 30%, nothing
// saturated); per-CTA critical path is, and __launch_bounds__ occ=16 capped
// regs at 32 -> ptxas couldn't pipeline the 16x-unrolled LDS/FMUL/STG body.
// R8: same thread->rule mapping, 256-thr CTAs at occ 8 (64-reg budget),
// h = t>>7 picks position half, r = t&127 picks rule. Grid 1024 = one wave,
// 56 warps/SM resident (same as R7), but 2x per-thread pipelining room.

static constexpr int F    = 15;           // membership functions per position
static constexpr int R    = 125;          // rules per position
static constexpr int G    = 32;           // positions per CTA
static constexpr int HP   = 16;           // positions per thread-half
static constexpr int NLD4 = G * F / 4;    // 120 float4 input loads per CTA

__global__ void __launch_bounds__(256, 8)
rules_fire_v8(const float4* __restrict__ x4, float* __restrict__ out)
{
    __shared__ float sx[G * F];           // 480 floats (32 rows x 15)

    const int t   = threadIdx.x;
    const int grp = blockIdx.x;

    // Stage 32x15 inputs (threads 0..119), zero->1 fix at load.
    if (t < NLD4) {
        float4 v = x4[(size_t)grp * NLD4 + t];
        v.x = (v.x == 0.0f) ? 1.0f : v.x;
        v.y = (v.y == 0.0f) ? 1.0f : v.y;
        v.z = (v.z == 0.0f) ? 1.0f : v.z;
        v.w = (v.w == 0.0f) ? 1.0f : v.w;
        reinterpret_cast<float4*>(sx)[t] = v;
    }
    __syncthreads();

    const int h = t >> 7;                 // which 16-position half
    const int r = t & 127;                // rule id within half

    if (r < R) {
        // One rule decomposition per thread — the only divisions in the kernel.
        const int q = r / 5;
        const int k = r - 5 * q;          // r % 5
        const int i = q / 5;
        const int j = q - 5 * i;          // (r/5) % 5

        const float* base = sx + h * HP * F;   // this half's 16 rows
        const int oa = i;
        const int ob = 5 + j;
        const int oc = 10 + k;

        float* o = out + (size_t)grp * G * R + h * HP * R + r;

        #pragma unroll
        for (int p = 0; p < HP; p++) {
            const int rb = p * F;              // folds into LDS immediates
            o[p * R] = base[rb + oa] * base[rb + ob] * base[rb + oc];
        }
    }
}

// Scalar fallback for positions past the last full group (unused for B=16,S=2048).
__global__ void rules_fire_tail(const float* __restrict__ x, float* __restrict__ out,
                                int pos0, int npos)
{
    const int pos = pos0 + blockIdx.x;
    if (pos >= npos) return;
    __shared__ float sxt[F + 1];
    const int t = threadIdx.x;
    if (t < F) {
        float v = x[(size_t)pos * F + t];
        sxt[t] = (v == 0.0f) ? 1.0f : v;
    }
    __syncthreads();
    if (t < R) {
        const int i = t / 25, j = (t / 5) % 5, k = t % 5;
        out[(size_t)pos * R + t] = sxt[i] * sxt[5 + j] * sxt[10 + k];
    }
}

extern "C" void kernel_launch(void* const* d_in, const int* in_sizes, int n_in,
                              void* d_out, int out_size)
{
    const float* x = (const float*)d_in[0];   // (B, S, 15) float32
    float* out = (float*)d_out;               // (B, S, 125) float32

    const int npos    = in_sizes[0] / F;      // 32768
    const int ngroups = npos / G;             // 1024
    if (ngroups > 0)
        rules_fire_v8<<<ngroups, 256>>>((const float4*)x, out);

    const int tail = npos - ngroups * G;
    if (tail > 0)
        rules_fire_tail<<<tail, 128>>>(x, out, ngroups * G, npos);
}